// round 14
// baseline (speedup 1.0000x reference)
#include <cuda_runtime.h>
#include <cuda_fp16.h>
#include <math.h>
#include <stdint.h>

#define EDIM 1024
#define NSEQ 2048
#define NBATCH 2
#define DH 64
#define NGROUPS 32   /* B * N_BLOCKS * MICRO_HEADS = 2*2*8 */

// Scratch (device globals: no allocation allowed in kernel_launch)
__device__ __half g_q[NGROUPS * NSEQ * DH];
__device__ __half g_k[NGROUPS * NSEQ * DH];
__device__ __half g_v[NGROUPS * NSEQ * DH];
__device__ __half g_ctx[NBATCH * NSEQ * EDIM];
__device__ __half g_xh[NBATCH * NSEQ * EDIM];   // fp16 x
__device__ __half g_wh[4 * EDIM * EDIM];        // fp16 Wq,Wk,Wv,Wo

// ---------------------------------------------------------------------------
// helpers
// ---------------------------------------------------------------------------
__device__ __forceinline__ void mma_f16(float* c, const uint32_t* a, const uint32_t* b) {
    asm volatile(
        "mma.sync.aligned.m16n8k16.row.col.f32.f16.f16.f32 "
        "{%0,%1,%2,%3}, {%4,%5,%6,%7}, {%8,%9}, {%0,%1,%2,%3};"
        : "+f"(c[0]), "+f"(c[1]), "+f"(c[2]), "+f"(c[3])
        : "r"(a[0]), "r"(a[1]), "r"(a[2]), "r"(a[3]), "r"(b[0]), "r"(b[1]));
}

__device__ __forceinline__ void ldsm_x4(uint32_t* r, uint32_t addr) {
    asm volatile("ldmatrix.sync.aligned.m8n8.x4.shared.b16 {%0,%1,%2,%3}, [%4];"
                 : "=r"(r[0]), "=r"(r[1]), "=r"(r[2]), "=r"(r[3]) : "r"(addr));
}
__device__ __forceinline__ void ldsm_x4_trans(uint32_t* r, uint32_t addr) {
    asm volatile("ldmatrix.sync.aligned.m8n8.x4.trans.shared.b16 {%0,%1,%2,%3}, [%4];"
                 : "=r"(r[0]), "=r"(r[1]), "=r"(r[2]), "=r"(r[3]) : "r"(addr));
}

__device__ __forceinline__ uint32_t pack_h2(float lo, float hi) {
    __half2 h = __floats2half2_rn(lo, hi);
    return *(uint32_t*)&h;
}

__device__ __forceinline__ uint32_t smem_u32(const void* p) {
    uint32_t a;
    asm("{ .reg .u64 t; cvta.to.shared.u64 t, %1; cvt.u32.u64 %0, t; }" : "=r"(a) : "l"(p));
    return a;
}

__device__ __forceinline__ void cp_async16(uint32_t dst, const void* src) {
    asm volatile("cp.async.cg.shared.global [%0], [%1], 16;" :: "r"(dst), "l"(src));
}
__device__ __forceinline__ void cp_commit() {
    asm volatile("cp.async.commit_group;" ::: "memory");
}
template<int N>
__device__ __forceinline__ void cp_wait() {
    asm volatile("cp.async.wait_group %0;" :: "n"(N) : "memory");
}

// ---------------------------------------------------------------------------
// Pre-convert pass: x and all W's -> fp16 (RN).
// ---------------------------------------------------------------------------
#define XF4 (NBATCH * NSEQ * EDIM / 4)   /* 1048576 */
#define WF4 (EDIM * EDIM / 4)            /*  262144 */
#define TOTF4 (XF4 + 4 * WF4)

__global__ __launch_bounds__(256)
void precvt(const float4* __restrict__ x,
            const float4* __restrict__ wq, const float4* __restrict__ wk,
            const float4* __restrict__ wv, const float4* __restrict__ wo,
            uint2* __restrict__ xh, uint2* __restrict__ wh)
{
    for (int i = blockIdx.x * blockDim.x + threadIdx.x; i < TOTF4;
         i += gridDim.x * blockDim.x) {
        const float4* src;
        uint2* dst;
        if (i < XF4) {
            src = x + i; dst = xh + i;
        } else {
            const int j = i - XF4;
            const int w = j / WF4, o = j - w * WF4;
            const float4* ws = (w == 0) ? wq : (w == 1) ? wk : (w == 2) ? wv : wo;
            src = ws + o; dst = wh + j;
        }
        float4 v = *src;
        union { __half2 h2[2]; uint2 u; } cv;
        cv.h2[0] = __floats2half2_rn(v.x, v.y);
        cv.h2[1] = __floats2half2_rn(v.z, v.w);
        *dst = cv.u;
    }
}

// ---------------------------------------------------------------------------
// fp16 HMMA GEMM: occupancy-2, 3-stage cp.async pipeline, BK=64 halfs,
// ldmatrix fragment loads. Prefetch fill hoisted BEFORE the MMA block.
// C[r][c] = alpha * (sum_k A[r][k] * W[c][k] + bias[c]),  A/W fp16, acc fp32.
// BM=128 BN=128, 256 threads, 8 warps (2m x 4n), warp 64x32.
// ---------------------------------------------------------------------------
#define BM 128
#define BN 128
#define BKH 64                          /* halfs per k-tile */
#define KSTH 72                         /* halfs row stride (=144 B) */
#define NKT (EDIM / BKH)                /* 16 */
#define NSTG 3
#define STGH ((BM + BN) * KSTH)         /* 18432 halfs = 36864 B per stage */
#define GEMM_SMEM (NSTG * STGH * 2)     /* 110592 bytes */

struct GemmJob  { const __half* W; const float* bias; void* C; float alpha; };
struct GemmJobs { GemmJob j[3]; };

template<bool SCRAMBLE>
__global__ __launch_bounds__(256, 2)
void gemm_mma(const __half* __restrict__ A, GemmJobs jobs)
{
    const GemmJob job = jobs.j[blockIdx.z];
    const __half* __restrict__ W   = job.W;
    const float* __restrict__ bias = job.bias;
    const float alpha              = job.alpha;

    extern __shared__ __half shh[];
    const uint32_t sb = smem_u32(shh);
    const int tid  = threadIdx.x;
    const int lane = tid & 31, wid = tid >> 5;
    const int g = lane >> 2, t = lane & 3;
    const int wm = (wid >> 2) * 64;          // warp m offset: 0 / 64
    const int wn = (wid & 3) * 32;           // warp n offset: 0/32/64/96
    const int rbase = blockIdx.y * BM;
    const int cbase = blockIdx.x * BN;

    // ldmatrix lane-address components
    const int aRow   = (lane & 15);
    const int aChunk = (lane >> 4) * 16;
    const int bRow   = (lane & 7) + (lane >> 4) * 8;
    const int bChunk = ((lane >> 3) & 1) * 16;

    auto fill = [&](int s, int kt) {
        const uint32_t stgA = sb + (uint32_t)(s * STGH) * 2u;
        const uint32_t stgB = stgA + (uint32_t)(BM * KSTH) * 2u;
#pragma unroll
        for (int j = 0; j < 4; j++) {
            const int idx = tid + j * 256;       // 0..1023
            const int r = idx >> 3, f = idx & 7;
            cp_async16(stgA + (uint32_t)(r * KSTH) * 2u + (uint32_t)f * 16u,
                       A + (size_t)(rbase + r) * EDIM + kt * BKH + f * 8);
        }
#pragma unroll
        for (int j = 0; j < 4; j++) {
            const int idx = tid + j * 256;
            const int r = idx >> 3, f = idx & 7;
            cp_async16(stgB + (uint32_t)(r * KSTH) * 2u + (uint32_t)f * 16u,
                       W + (size_t)(cbase + r) * EDIM + kt * BKH + f * 8);
        }
        cp_commit();
    };

    float accf[4][4][4];
#pragma unroll
    for (int mt = 0; mt < 4; mt++)
#pragma unroll
        for (int nt = 0; nt < 4; nt++)
#pragma unroll
            for (int q = 0; q < 4; q++) accf[mt][nt][q] = 0.f;

    fill(0, 0);
    fill(1, 1);

#pragma unroll 1
    for (int kt = 0; kt < NKT; kt++) {
        const int s = (kt % NSTG);
        if (kt == NKT - 1) cp_wait<0>();
        else               cp_wait<1>();
        __syncthreads();

        // hoisted prefetch: start the kt+2 global loads before the MMA block
        if (kt + 2 < NKT) fill((kt + 2) % NSTG, kt + 2);

        const uint32_t aBase = sb + (uint32_t)(s * STGH) * 2u;
        const uint32_t bBase = aBase + (uint32_t)(BM * KSTH) * 2u;
#pragma unroll
        for (int ks = 0; ks < 4; ks++) {         // four k16 steps cover BKH=64
            uint32_t af[4][4], bf[4][2];
#pragma unroll
            for (int mt = 0; mt < 4; mt++) {
                const uint32_t addr = aBase
                    + (uint32_t)((wm + mt * 16 + aRow) * KSTH) * 2u
                    + (uint32_t)(ks * 32 + aChunk);
                ldsm_x4(af[mt], addr);
            }
#pragma unroll
            for (int ntp = 0; ntp < 2; ntp++) {
                uint32_t r4[4];
                const uint32_t addr = bBase
                    + (uint32_t)((wn + ntp * 16 + bRow) * KSTH) * 2u
                    + (uint32_t)(ks * 32 + bChunk);
                ldsm_x4(r4, addr);
                bf[2 * ntp][0] = r4[0]; bf[2 * ntp][1] = r4[1];
                bf[2 * ntp + 1][0] = r4[2]; bf[2 * ntp + 1][1] = r4[3];
            }
#pragma unroll
            for (int mt = 0; mt < 4; mt++)
#pragma unroll
                for (int nt = 0; nt < 4; nt++)
                    mma_f16(accf[mt][nt], af[mt], bf[nt]);
        }
    }

    // epilogue: c0=(g,2t) c1=(g,2t+1) c2=(g+8,2t) c3=(g+8,2t+1)
#pragma unroll
    for (int nt = 0; nt < 4; nt++) {
        const int col = cbase + wn + nt * 8 + 2 * t;
        const float2 bb = *(const float2*)&bias[col];
#pragma unroll
        for (int mt = 0; mt < 4; mt++) {
#pragma unroll
            for (int h = 0; h < 2; h++) {
                const int r = rbase + wm + mt * 16 + g + h * 8;
                const float vx = alpha * (accf[mt][nt][h * 2 + 0] + bb.x);
                const float vy = alpha * (accf[mt][nt][h * 2 + 1] + bb.y);
                if (SCRAMBLE) {
                    __half* Ch = (__half*)job.C;
                    const int b_ = r >> 11;
                    const int n  = r & (NSEQ - 1);
                    const int gb = col >> 9;
                    const int mm = (col >> 6) & 7;
                    const int dd = col & 63;
                    const int flat = n * 8 + mm;
                    const int mp = flat >> 11;
                    const int np = flat & (NSEQ - 1);
                    *(__half2*)(Ch + ((size_t)((b_ * 2 + gb) * 8 + mp) * NSEQ + np) * DH + dd) =
                        __floats2half2_rn(vx, vy);
                } else {
                    float* Cf = (float*)job.C;
                    float2 v; v.x = vx; v.y = vy;
                    *(float2*)(Cf + (size_t)r * EDIM + col) = v;
                }
            }
        }
    }
}

// ---------------------------------------------------------------------------
// Flash attention on fp16 HMMA m16n8k16 with ldmatrix loads and
// REGISTER-DIRECT P fragments (S C-fragment layout == PV A-fragment layout,
// so P never round-trips through smem; no __syncwarp needed).
// Br=128 (8 warps x m16), dh=64. KV in 128-row double-buffered tiles,
// processed as two 64-column halves. V frags via ldmatrix.x4.trans.
// ---------------------------------------------------------------------------
#define KSTRH 72          /* halfs row stride = 144 B */
#define VSTRH 72
#define PSTRH 72
#define OFF_K0 0
#define OFF_K1 (128 * KSTRH)                     /*  9216 halfs */
#define OFF_V0 (2 * 128 * KSTRH)                 /* 18432 */
#define OFF_V1 (OFF_V0 + 128 * VSTRH)            /* 27648 */
#define OFF_QP (OFF_V0 + 2 * 128 * VSTRH)        /* 36864 */
#define ATTN_SMEM ((OFF_QP + 128 * PSTRH) * 2)   /* 92160 bytes */

__global__ __launch_bounds__(256, 2)
void attn_mma(__half* __restrict__ ctx)
{
    extern __shared__ __half shh[];
    const uint32_t sb = smem_u32(shh);
    const int tid  = threadIdx.x;
    const int lane = tid & 31, wid = tid >> 5;
    const int g = lane >> 2, t = lane & 3;
    const int qblk = (int)gridDim.x - 1 - (int)blockIdx.x;   // long first
    const int bgm  = blockIdx.y;

    const __half* Qb = g_q + (size_t)bgm * NSEQ * DH;
    const __half* Kb = g_k + (size_t)bgm * NSEQ * DH;
    const __half* Vb = g_v + (size_t)bgm * NSEQ * DH;

    const uint32_t koff[2] = { OFF_K0 * 2u, OFF_K1 * 2u };
    const uint32_t voff[2] = { OFF_V0 * 2u, OFF_V1 * 2u };

    // ldmatrix lane-address components
    const int aRow   = (lane & 15);
    const int aChunk = (lane >> 4) * 16;
    const int bRow   = (lane & 7) + (lane >> 4) * 8;
    const int bChunk = ((lane >> 3) & 1) * 16;
    const int vRow   = (lane & 7) + ((lane >> 3) & 1) * 8;   // k within 16
    const int vChunk = (lane >> 4) * 16;                      // n halfs *2 bytes

    const int njb = qblk + 1;    // 128-row kv tiles (incl. diagonal)

    {
#pragma unroll
        for (int i = 0; i < 4; i++) {
            const int idx = tid + i * 256;           // 0..1023
            const int r = idx >> 3, f = idx & 7;
            cp_async16(sb + koff[0] + (uint32_t)(r * KSTRH) * 2u + (uint32_t)f * 16u,
                       Kb + (size_t)r * DH + f * 8);
        }
#pragma unroll
        for (int i = 0; i < 4; i++) {
            const int idx = tid + i * 256;
            const int r = idx >> 3, f = idx & 7;
            cp_async16(sb + voff[0] + (uint32_t)(r * VSTRH) * 2u + (uint32_t)f * 16u,
                       Vb + (size_t)r * DH + f * 8);
        }
        cp_commit();
    }

    // load Q tile (128 x 64 halfs) into QP staging
    {
        __half* QP = shh + OFF_QP;
#pragma unroll
        for (int i = 0; i < 4; i++) {
            const int idx = tid + i * 256;           // 0..1023
            const int r = idx >> 3, f = idx & 7;
            *(float4*)&QP[r * PSTRH + f * 8] =
                *(const float4*)(Qb + (size_t)(qblk * 128 + r) * DH + f * 8);
        }
    }
    __syncthreads();

    // Q A-fragments via ldmatrix: 4 k16-steps x 4 regs
    uint32_t qf[4][4];
    {
        const uint32_t qBase = sb + OFF_QP * 2u;
#pragma unroll
        for (int st = 0; st < 4; st++) {
            const uint32_t addr = qBase
                + (uint32_t)((16 * wid + aRow) * PSTRH) * 2u
                + (uint32_t)(st * 32 + aChunk);
            ldsm_x4(qf[st], addr);
        }
    }

    float m_i[2] = { -INFINITY, -INFINITY };
    float l_i[2] = { 0.f, 0.f };
    float Oa[8][4];
#pragma unroll
    for (int nt = 0; nt < 8; nt++)
#pragma unroll
        for (int q = 0; q < 4; q++) Oa[nt][q] = 0.f;

#pragma unroll 1
    for (int jt = 0; jt < njb; jt++) {
        const int cur = jt & 1;
        cp_wait<0>();
        __syncthreads();

        if (jt + 1 < njb) {
            const int nxt = (jt + 1) & 1;
            const __half* Ksrc = Kb + (size_t)(jt + 1) * 128 * DH;
            const __half* Vsrc = Vb + (size_t)(jt + 1) * 128 * DH;
#pragma unroll
            for (int i = 0; i < 4; i++) {
                const int idx = tid + i * 256;
                const int r = idx >> 3, f = idx & 7;
                cp_async16(sb + koff[nxt] + (uint32_t)(r * KSTRH) * 2u + (uint32_t)f * 16u,
                           Ksrc + (size_t)r * DH + f * 8);
            }
#pragma unroll
            for (int i = 0; i < 4; i++) {
                const int idx = tid + i * 256;
                const int r = idx >> 3, f = idx & 7;
                cp_async16(sb + voff[nxt] + (uint32_t)(r * VSTRH) * 2u + (uint32_t)f * 16u,
                           Vsrc + (size_t)r * DH + f * 8);
            }
            cp_commit();
        }

#pragma unroll 1
        for (int half = 0; half < 2; half++) {
            const int jb = 2 * jt + half;            // 64-col tile index
            const bool active = !(jb == 2 * qblk + 1 && wid < 4);
            if (active) {
                // ---- S = Q K^T ----
                float Sa[8][4];
#pragma unroll
                for (int nt = 0; nt < 8; nt++)
#pragma unroll
                    for (int q = 0; q < 4; q++) Sa[nt][q] = 0.f;

                const uint32_t kBase = sb + (cur ? OFF_K1 : OFF_K0) * 2u
                                     + (uint32_t)(half * 64 * KSTRH) * 2u;
#pragma unroll
                for (int st = 0; st < 4; st++) {
#pragma unroll
                    for (int ntp = 0; ntp < 4; ntp++) {
                        uint32_t r4[4];
                        const uint32_t addr = kBase
                            + (uint32_t)((ntp * 16 + bRow) * KSTRH) * 2u
                            + (uint32_t)(st * 32 + bChunk);
                        ldsm_x4(r4, addr);
                        mma_f16(Sa[2 * ntp], qf[st], r4);
                        mma_f16(Sa[2 * ntp + 1], qf[st], r4 + 2);
                    }
                }

                // ---- causal mask ----
                if (jb >= 2 * qblk) {
                    const int colb = jb * 64 + 2 * t;
                    const int rowb = qblk * 128 + 16 * wid + g;
#pragma unroll
                    for (int nt = 0; nt < 8; nt++) {
                        const int c0 = colb + nt * 8;
                        if (c0 > rowb)     Sa[nt][0] = -INFINITY;
                        if (c0 + 1 > rowb) Sa[nt][1] = -INFINITY;
                        if (c0 > rowb + 8)     Sa[nt][2] = -INFINITY;
                        if (c0 + 1 > rowb + 8) Sa[nt][3] = -INFINITY;
                    }
                }

                // ---- online softmax (P stays in Sa registers) ----
#pragma unroll
                for (int h = 0; h < 2; h++) {
                    float rmax = -INFINITY;
#pragma unroll
                    for (int nt = 0; nt < 8; nt++)
                        rmax = fmaxf(rmax, fmaxf(Sa[nt][2 * h], Sa[nt][2 * h + 1]));
                    rmax = fmaxf(rmax, __shfl_xor_sync(0xffffffffu, rmax, 1));
                    rmax = fmaxf(rmax, __shfl_xor_sync(0xffffffffu, rmax, 2));
                    const float mnew = fmaxf(m_i[h], rmax);
                    const float a = __expf(m_i[h] - mnew);
                    float rs = 0.f;
#pragma unroll
                    for (int nt = 0; nt < 8; nt++) {
                        const float p0 = __expf(Sa[nt][2 * h]     - mnew);
                        const float p1 = __expf(Sa[nt][2 * h + 1] - mnew);
                        Sa[nt][2 * h] = p0; Sa[nt][2 * h + 1] = p1;
                        rs += p0 + p1;
                    }
                    rs += __shfl_xor_sync(0xffffffffu, rs, 1);
                    rs += __shfl_xor_sync(0xffffffffu, rs, 2);
                    l_i[h] = l_i[h] * a + rs;
                    m_i[h] = mnew;
#pragma unroll
                    for (int nt = 0; nt < 8; nt++) {
                        Oa[nt][2 * h] *= a;
                        Oa[nt][2 * h + 1] *= a;
                    }
                }

                // ---- O += P V ----  (P A-frags packed directly from Sa:
                //  C-layout {(g,2t),(g,2t+1),(g+8,2t),(g+8,2t+1)} at nt=2st/2st+1
                //  == A-layout {a0,a1,a2,a3} for k16-step st)
                const uint32_t vBase = sb + (cur ? OFF_V1 : OFF_V0) * 2u
                                     + (uint32_t)(half * 64 * VSTRH) * 2u;
#pragma unroll
                for (int st = 0; st < 4; st++) {
                    uint32_t pa[4];
                    pa[0] = pack_h2(Sa[2 * st][0],     Sa[2 * st][1]);
                    pa[1] = pack_h2(Sa[2 * st][2],     Sa[2 * st][3]);
                    pa[2] = pack_h2(Sa[2 * st + 1][0], Sa[2 * st + 1][1]);
                    pa[3] = pack_h2(Sa[2 * st + 1][2], Sa[2 * st + 1][3]);
#pragma unroll
                    for (int ntp = 0; ntp < 4; ntp++) {
                        uint32_t vb[4];
                        const uint32_t addr = vBase
                            + (uint32_t)((st * 16 + vRow) * VSTRH) * 2u
                            + (uint32_t)((ntp * 16) * 2 + vChunk);
                        ldsm_x4_trans(vb, addr);
                        mma_f16(Oa[2 * ntp], pa, vb);
                        mma_f16(Oa[2 * ntp + 1], pa, vb + 2);
                    }
                }
            }
        }
    }

    // epilogue: normalize, write ctx (fp16, feeds O-GEMM) UNSCRAMBLED
    const int b_ = bgm >> 4;
    const int gb = (bgm >> 3) & 1;
    const int mp = bgm & 7;
#pragma unroll
    for (int h = 0; h < 2; h++) {
        const float inv = 1.0f / l_i[h];
        const int np = qblk * 128 + 16 * wid + g + 8 * h;
        const int flat = mp * NSEQ + np;
        const int n  = flat >> 3;
        const int mm = flat & 7;
        const int colbase = gb * 512 + mm * 64 + 2 * t;
        __half* dst = ctx + (size_t)(b_ * NSEQ + n) * EDIM;
#pragma unroll
        for (int nt = 0; nt < 8; nt++) {
            *(__half2*)(dst + colbase + nt * 8) =
                __floats2half2_rn(Oa[nt][2 * h] * inv, Oa[nt][2 * h + 1] * inv);
        }
    }
}

// ---------------------------------------------------------------------------

extern "C" void kernel_launch(void* const* d_in, const int* in_sizes, int n_in,
                              void* d_out, int out_size) {
    (void)in_sizes; (void)n_in; (void)out_size;
    const float* x  = (const float*)d_in[0];
    const float* Wq = (const float*)d_in[1];
    const float* bq = (const float*)d_in[2];
    const float* Wk = (const float*)d_in[3];
    const float* bk = (const float*)d_in[4];
    const float* Wv = (const float*)d_in[5];
    const float* bv = (const float*)d_in[6];
    const float* Wo = (const float*)d_in[7];
    const float* bo = (const float*)d_in[8];
    float* out = (float*)d_out;

    __half *pq, *pk, *pv, *pctx, *pxh, *pwh;
    cudaGetSymbolAddress((void**)&pq,   g_q);
    cudaGetSymbolAddress((void**)&pk,   g_k);
    cudaGetSymbolAddress((void**)&pv,   g_v);
    cudaGetSymbolAddress((void**)&pctx, g_ctx);
    cudaGetSymbolAddress((void**)&pxh,  g_xh);
    cudaGetSymbolAddress((void**)&pwh,  g_wh);

    cudaFuncSetAttribute(gemm_mma<true>,
                         cudaFuncAttributeMaxDynamicSharedMemorySize, GEMM_SMEM);
    cudaFuncSetAttribute(gemm_mma<false>,
                         cudaFuncAttributeMaxDynamicSharedMemorySize, GEMM_SMEM);
    cudaFuncSetAttribute(attn_mma,
                         cudaFuncAttributeMaxDynamicSharedMemorySize, ATTN_SMEM);

    // 1) convert x and all W's to fp16 scratch
    precvt<<<2048, 256>>>((const float4*)x,
                          (const float4*)Wq, (const float4*)Wk,
                          (const float4*)Wv, (const float4*)Wo,
                          (uint2*)pxh, (uint2*)pwh);

    const float scale = 0.125f;  // dh^-0.5, folded into Q (and its bias)

    // 2) QKV projections (fused z-grid), fp16 in / fp16 scrambled out
    GemmJobs qkv;
    qkv.j[0] = { pwh + 0 * (size_t)EDIM * EDIM, bq, pq, scale };
    qkv.j[1] = { pwh + 1 * (size_t)EDIM * EDIM, bk, pk, 1.0f };
    qkv.j[2] = { pwh + 2 * (size_t)EDIM * EDIM, bv, pv, 1.0f };
    gemm_mma<true><<<dim3(EDIM / BN, (NBATCH * NSEQ) / BM, 3), 256, GEMM_SMEM>>>(pxh, qkv);

    // 3) attention (fp16 operands, fp32 softmax/accum)
    attn_mma<<<dim3(NSEQ / 128, NGROUPS), 256, ATTN_SMEM>>>(pctx);

    // 4) output projection: fp16 ctx x fp16 Wo -> fp32 out
    GemmJobs oj;
    oj.j[0] = { pwh + 3 * (size_t)EDIM * EDIM, bo, out, 1.0f };
    oj.j[1] = oj.j[0];
    oj.j[2] = oj.j[0];
    gemm_mma<false><<<dim3(EDIM / BN, (NBATCH * NSEQ) / BM, 1), 256, GEMM_SMEM>>>(pctx, oj);
}

// round 15
// speedup vs baseline: 1.0383x; 1.0383x over previous
#include <cuda_runtime.h>
#include <cuda_fp16.h>
#include <math.h>
#include <stdint.h>

#define EDIM 1024
#define NSEQ 2048
#define NBATCH 2
#define DH 64
#define NGROUPS 32   /* B * N_BLOCKS * MICRO_HEADS = 2*2*8 */

// Scratch (device globals: no allocation allowed in kernel_launch)
__device__ __half g_q[NGROUPS * NSEQ * DH];
__device__ __half g_k[NGROUPS * NSEQ * DH];
__device__ __half g_v[NGROUPS * NSEQ * DH];
__device__ __half g_ctx[NBATCH * NSEQ * EDIM];
__device__ __half g_xh[NBATCH * NSEQ * EDIM];   // fp16 x
__device__ __half g_wh[4 * EDIM * EDIM];        // fp16 Wq,Wk,Wv,Wo

// ---------------------------------------------------------------------------
// helpers
// ---------------------------------------------------------------------------
__device__ __forceinline__ void mma_f16(float* c, const uint32_t* a, const uint32_t* b) {
    asm volatile(
        "mma.sync.aligned.m16n8k16.row.col.f32.f16.f16.f32 "
        "{%0,%1,%2,%3}, {%4,%5,%6,%7}, {%8,%9}, {%0,%1,%2,%3};"
        : "+f"(c[0]), "+f"(c[1]), "+f"(c[2]), "+f"(c[3])
        : "r"(a[0]), "r"(a[1]), "r"(a[2]), "r"(a[3]), "r"(b[0]), "r"(b[1]));
}

__device__ __forceinline__ void ldsm_x4(uint32_t* r, uint32_t addr) {
    asm volatile("ldmatrix.sync.aligned.m8n8.x4.shared.b16 {%0,%1,%2,%3}, [%4];"
                 : "=r"(r[0]), "=r"(r[1]), "=r"(r[2]), "=r"(r[3]) : "r"(addr));
}
__device__ __forceinline__ void ldsm_x4_trans(uint32_t* r, uint32_t addr) {
    asm volatile("ldmatrix.sync.aligned.m8n8.x4.trans.shared.b16 {%0,%1,%2,%3}, [%4];"
                 : "=r"(r[0]), "=r"(r[1]), "=r"(r[2]), "=r"(r[3]) : "r"(addr));
}

__device__ __forceinline__ uint32_t pack_h2(float lo, float hi) {
    __half2 h = __floats2half2_rn(lo, hi);
    return *(uint32_t*)&h;
}

__device__ __forceinline__ uint32_t smem_u32(const void* p) {
    uint32_t a;
    asm("{ .reg .u64 t; cvta.to.shared.u64 t, %1; cvt.u32.u64 %0, t; }" : "=r"(a) : "l"(p));
    return a;
}

__device__ __forceinline__ void cp_async16(uint32_t dst, const void* src) {
    asm volatile("cp.async.cg.shared.global [%0], [%1], 16;" :: "r"(dst), "l"(src));
}
__device__ __forceinline__ void cp_commit() {
    asm volatile("cp.async.commit_group;" ::: "memory");
}
template<int N>
__device__ __forceinline__ void cp_wait() {
    asm volatile("cp.async.wait_group %0;" :: "n"(N) : "memory");
}

// ---------------------------------------------------------------------------
// Pre-convert pass: x and all W's -> fp16 (RN).
// ---------------------------------------------------------------------------
#define XF4 (NBATCH * NSEQ * EDIM / 4)   /* 1048576 */
#define WF4 (EDIM * EDIM / 4)            /*  262144 */
#define TOTF4 (XF4 + 4 * WF4)

__global__ __launch_bounds__(256)
void precvt(const float4* __restrict__ x,
            const float4* __restrict__ wq, const float4* __restrict__ wk,
            const float4* __restrict__ wv, const float4* __restrict__ wo,
            uint2* __restrict__ xh, uint2* __restrict__ wh)
{
    for (int i = blockIdx.x * blockDim.x + threadIdx.x; i < TOTF4;
         i += gridDim.x * blockDim.x) {
        const float4* src;
        uint2* dst;
        if (i < XF4) {
            src = x + i; dst = xh + i;
        } else {
            const int j = i - XF4;
            const int w = j / WF4, o = j - w * WF4;
            const float4* ws = (w == 0) ? wq : (w == 1) ? wk : (w == 2) ? wv : wo;
            src = ws + o; dst = wh + j;
        }
        float4 v = *src;
        union { __half2 h2[2]; uint2 u; } cv;
        cv.h2[0] = __floats2half2_rn(v.x, v.y);
        cv.h2[1] = __floats2half2_rn(v.z, v.w);
        *dst = cv.u;
    }
}

// ---------------------------------------------------------------------------
// fp16 HMMA GEMM: occupancy-2, 3-stage cp.async pipeline, BK=64 halfs,
// ldmatrix fragment loads. Prefetch fill issued after the FIRST ks block
// (mid-loop: lets post-barrier fragment loads + first MMAs start instantly,
// then overlaps the LSU burst under the remaining 48 MMAs).
// C[r][c] = alpha * (sum_k A[r][k] * W[c][k] + bias[c]),  A/W fp16, acc fp32.
// BM=128 BN=128, 256 threads, 8 warps (2m x 4n), warp 64x32.
// ---------------------------------------------------------------------------
#define BM 128
#define BN 128
#define BKH 64                          /* halfs per k-tile */
#define KSTH 72                         /* halfs row stride (=144 B) */
#define NKT (EDIM / BKH)                /* 16 */
#define NSTG 3
#define STGH ((BM + BN) * KSTH)         /* 18432 halfs = 36864 B per stage */
#define GEMM_SMEM (NSTG * STGH * 2)     /* 110592 bytes */

struct GemmJob  { const __half* W; const float* bias; void* C; float alpha; };
struct GemmJobs { GemmJob j[3]; };

template<bool SCRAMBLE>
__global__ __launch_bounds__(256, 2)
void gemm_mma(const __half* __restrict__ A, GemmJobs jobs)
{
    const GemmJob job = jobs.j[blockIdx.z];
    const __half* __restrict__ W   = job.W;
    const float* __restrict__ bias = job.bias;
    const float alpha              = job.alpha;

    extern __shared__ __half shh[];
    const uint32_t sb = smem_u32(shh);
    const int tid  = threadIdx.x;
    const int lane = tid & 31, wid = tid >> 5;
    const int g = lane >> 2, t = lane & 3;
    const int wm = (wid >> 2) * 64;          // warp m offset: 0 / 64
    const int wn = (wid & 3) * 32;           // warp n offset: 0/32/64/96
    const int rbase = blockIdx.y * BM;
    const int cbase = blockIdx.x * BN;

    // ldmatrix lane-address components
    const int aRow   = (lane & 15);
    const int aChunk = (lane >> 4) * 16;
    const int bRow   = (lane & 7) + (lane >> 4) * 8;
    const int bChunk = ((lane >> 3) & 1) * 16;

    auto fill = [&](int s, int kt) {
        const uint32_t stgA = sb + (uint32_t)(s * STGH) * 2u;
        const uint32_t stgB = stgA + (uint32_t)(BM * KSTH) * 2u;
#pragma unroll
        for (int j = 0; j < 4; j++) {
            const int idx = tid + j * 256;       // 0..1023
            const int r = idx >> 3, f = idx & 7;
            cp_async16(stgA + (uint32_t)(r * KSTH) * 2u + (uint32_t)f * 16u,
                       A + (size_t)(rbase + r) * EDIM + kt * BKH + f * 8);
        }
#pragma unroll
        for (int j = 0; j < 4; j++) {
            const int idx = tid + j * 256;
            const int r = idx >> 3, f = idx & 7;
            cp_async16(stgB + (uint32_t)(r * KSTH) * 2u + (uint32_t)f * 16u,
                       W + (size_t)(cbase + r) * EDIM + kt * BKH + f * 8);
        }
        cp_commit();
    };

    float accf[4][4][4];
#pragma unroll
    for (int mt = 0; mt < 4; mt++)
#pragma unroll
        for (int nt = 0; nt < 4; nt++)
#pragma unroll
            for (int q = 0; q < 4; q++) accf[mt][nt][q] = 0.f;

    fill(0, 0);
    fill(1, 1);

#pragma unroll 1
    for (int kt = 0; kt < NKT; kt++) {
        const int s = (kt % NSTG);
        if (kt == NKT - 1) cp_wait<0>();
        else               cp_wait<1>();
        __syncthreads();

        const uint32_t aBase = sb + (uint32_t)(s * STGH) * 2u;
        const uint32_t bBase = aBase + (uint32_t)(BM * KSTH) * 2u;
#pragma unroll
        for (int ks = 0; ks < 4; ks++) {         // four k16 steps cover BKH=64
            uint32_t af[4][4], bf[4][2];
#pragma unroll
            for (int mt = 0; mt < 4; mt++) {
                const uint32_t addr = aBase
                    + (uint32_t)((wm + mt * 16 + aRow) * KSTH) * 2u
                    + (uint32_t)(ks * 32 + aChunk);
                ldsm_x4(af[mt], addr);
            }
#pragma unroll
            for (int ntp = 0; ntp < 2; ntp++) {
                uint32_t r4[4];
                const uint32_t addr = bBase
                    + (uint32_t)((wn + ntp * 16 + bRow) * KSTH) * 2u
                    + (uint32_t)(ks * 32 + bChunk);
                ldsm_x4(r4, addr);
                bf[2 * ntp][0] = r4[0]; bf[2 * ntp][1] = r4[1];
                bf[2 * ntp + 1][0] = r4[2]; bf[2 * ntp + 1][1] = r4[3];
            }
#pragma unroll
            for (int mt = 0; mt < 4; mt++)
#pragma unroll
                for (int nt = 0; nt < 4; nt++)
                    mma_f16(accf[mt][nt], af[mt], bf[nt]);

            // mid-loop prefetch: after the first ks block's MMAs are issued
            if (ks == 0 && kt + 2 < NKT) fill((kt + 2) % NSTG, kt + 2);
        }
    }

    // epilogue: c0=(g,2t) c1=(g,2t+1) c2=(g+8,2t) c3=(g+8,2t+1)
#pragma unroll
    for (int nt = 0; nt < 4; nt++) {
        const int col = cbase + wn + nt * 8 + 2 * t;
        const float2 bb = *(const float2*)&bias[col];
#pragma unroll
        for (int mt = 0; mt < 4; mt++) {
#pragma unroll
            for (int h = 0; h < 2; h++) {
                const int r = rbase + wm + mt * 16 + g + h * 8;
                const float vx = alpha * (accf[mt][nt][h * 2 + 0] + bb.x);
                const float vy = alpha * (accf[mt][nt][h * 2 + 1] + bb.y);
                if (SCRAMBLE) {
                    __half* Ch = (__half*)job.C;
                    const int b_ = r >> 11;
                    const int n  = r & (NSEQ - 1);
                    const int gb = col >> 9;
                    const int mm = (col >> 6) & 7;
                    const int dd = col & 63;
                    const int flat = n * 8 + mm;
                    const int mp = flat >> 11;
                    const int np = flat & (NSEQ - 1);
                    *(__half2*)(Ch + ((size_t)((b_ * 2 + gb) * 8 + mp) * NSEQ + np) * DH + dd) =
                        __floats2half2_rn(vx, vy);
                } else {
                    float* Cf = (float*)job.C;
                    float2 v; v.x = vx; v.y = vy;
                    *(float2*)(Cf + (size_t)r * EDIM + col) = v;
                }
            }
        }
    }
}

// ---------------------------------------------------------------------------
// Flash attention on fp16 HMMA m16n8k16 with ldmatrix loads and
// REGISTER-DIRECT P fragments (S C-fragment layout == PV A-fragment layout,
// so P never round-trips through smem; no __syncwarp needed).
// Br=128 (8 warps x m16), dh=64. KV in 128-row double-buffered tiles,
// processed as two 64-column halves. V frags via ldmatrix.x4.trans.
// (byte-identical to the R13 kernel)
// ---------------------------------------------------------------------------
#define KSTRH 72          /* halfs row stride = 144 B */
#define VSTRH 72
#define PSTRH 72
#define OFF_K0 0
#define OFF_K1 (128 * KSTRH)                     /*  9216 halfs */
#define OFF_V0 (2 * 128 * KSTRH)                 /* 18432 */
#define OFF_V1 (OFF_V0 + 128 * VSTRH)            /* 27648 */
#define OFF_QP (OFF_V0 + 2 * 128 * VSTRH)        /* 36864 */
#define ATTN_SMEM ((OFF_QP + 128 * PSTRH) * 2)   /* 92160 bytes */

__global__ __launch_bounds__(256, 2)
void attn_mma(__half* __restrict__ ctx)
{
    extern __shared__ __half shh[];
    const uint32_t sb = smem_u32(shh);
    const int tid  = threadIdx.x;
    const int lane = tid & 31, wid = tid >> 5;
    const int g = lane >> 2, t = lane & 3;
    const int qblk = (int)gridDim.x - 1 - (int)blockIdx.x;   // long first
    const int bgm  = blockIdx.y;

    const __half* Qb = g_q + (size_t)bgm * NSEQ * DH;
    const __half* Kb = g_k + (size_t)bgm * NSEQ * DH;
    const __half* Vb = g_v + (size_t)bgm * NSEQ * DH;

    const uint32_t koff[2] = { OFF_K0 * 2u, OFF_K1 * 2u };
    const uint32_t voff[2] = { OFF_V0 * 2u, OFF_V1 * 2u };

    // ldmatrix lane-address components
    const int aRow   = (lane & 15);
    const int aChunk = (lane >> 4) * 16;
    const int bRow   = (lane & 7) + (lane >> 4) * 8;
    const int bChunk = ((lane >> 3) & 1) * 16;
    const int vRow   = (lane & 7) + ((lane >> 3) & 1) * 8;   // k within 16
    const int vChunk = (lane >> 4) * 16;                      // n halfs *2 bytes

    const int njb = qblk + 1;    // 128-row kv tiles (incl. diagonal)

    {
#pragma unroll
        for (int i = 0; i < 4; i++) {
            const int idx = tid + i * 256;           // 0..1023
            const int r = idx >> 3, f = idx & 7;
            cp_async16(sb + koff[0] + (uint32_t)(r * KSTRH) * 2u + (uint32_t)f * 16u,
                       Kb + (size_t)r * DH + f * 8);
        }
#pragma unroll
        for (int i = 0; i < 4; i++) {
            const int idx = tid + i * 256;
            const int r = idx >> 3, f = idx & 7;
            cp_async16(sb + voff[0] + (uint32_t)(r * VSTRH) * 2u + (uint32_t)f * 16u,
                       Vb + (size_t)r * DH + f * 8);
        }
        cp_commit();
    }

    // load Q tile (128 x 64 halfs) into QP staging
    {
        __half* QP = shh + OFF_QP;
#pragma unroll
        for (int i = 0; i < 4; i++) {
            const int idx = tid + i * 256;           // 0..1023
            const int r = idx >> 3, f = idx & 7;
            *(float4*)&QP[r * PSTRH + f * 8] =
                *(const float4*)(Qb + (size_t)(qblk * 128 + r) * DH + f * 8);
        }
    }
    __syncthreads();

    // Q A-fragments via ldmatrix: 4 k16-steps x 4 regs
    uint32_t qf[4][4];
    {
        const uint32_t qBase = sb + OFF_QP * 2u;
#pragma unroll
        for (int st = 0; st < 4; st++) {
            const uint32_t addr = qBase
                + (uint32_t)((16 * wid + aRow) * PSTRH) * 2u
                + (uint32_t)(st * 32 + aChunk);
            ldsm_x4(qf[st], addr);
        }
    }

    float m_i[2] = { -INFINITY, -INFINITY };
    float l_i[2] = { 0.f, 0.f };
    float Oa[8][4];
#pragma unroll
    for (int nt = 0; nt < 8; nt++)
#pragma unroll
        for (int q = 0; q < 4; q++) Oa[nt][q] = 0.f;

#pragma unroll 1
    for (int jt = 0; jt < njb; jt++) {
        const int cur = jt & 1;
        cp_wait<0>();
        __syncthreads();

        if (jt + 1 < njb) {
            const int nxt = (jt + 1) & 1;
            const __half* Ksrc = Kb + (size_t)(jt + 1) * 128 * DH;
            const __half* Vsrc = Vb + (size_t)(jt + 1) * 128 * DH;
#pragma unroll
            for (int i = 0; i < 4; i++) {
                const int idx = tid + i * 256;
                const int r = idx >> 3, f = idx & 7;
                cp_async16(sb + koff[nxt] + (uint32_t)(r * KSTRH) * 2u + (uint32_t)f * 16u,
                           Ksrc + (size_t)r * DH + f * 8);
            }
#pragma unroll
            for (int i = 0; i < 4; i++) {
                const int idx = tid + i * 256;
                const int r = idx >> 3, f = idx & 7;
                cp_async16(sb + voff[nxt] + (uint32_t)(r * VSTRH) * 2u + (uint32_t)f * 16u,
                           Vsrc + (size_t)r * DH + f * 8);
            }
            cp_commit();
        }

#pragma unroll 1
        for (int half = 0; half < 2; half++) {
            const int jb = 2 * jt + half;            // 64-col tile index
            const bool active = !(jb == 2 * qblk + 1 && wid < 4);
            if (active) {
                // ---- S = Q K^T ----
                float Sa[8][4];
#pragma unroll
                for (int nt = 0; nt < 8; nt++)
#pragma unroll
                    for (int q = 0; q < 4; q++) Sa[nt][q] = 0.f;

                const uint32_t kBase = sb + (cur ? OFF_K1 : OFF_K0) * 2u
                                     + (uint32_t)(half * 64 * KSTRH) * 2u;
#pragma unroll
                for (int st = 0; st < 4; st++) {
#pragma unroll
                    for (int ntp = 0; ntp < 4; ntp++) {
                        uint32_t r4[4];
                        const uint32_t addr = kBase
                            + (uint32_t)((ntp * 16 + bRow) * KSTRH) * 2u
                            + (uint32_t)(st * 32 + bChunk);
                        ldsm_x4(r4, addr);
                        mma_f16(Sa[2 * ntp], qf[st], r4);
                        mma_f16(Sa[2 * ntp + 1], qf[st], r4 + 2);
                    }
                }

                // ---- causal mask ----
                if (jb >= 2 * qblk) {
                    const int colb = jb * 64 + 2 * t;
                    const int rowb = qblk * 128 + 16 * wid + g;
#pragma unroll
                    for (int nt = 0; nt < 8; nt++) {
                        const int c0 = colb + nt * 8;
                        if (c0 > rowb)     Sa[nt][0] = -INFINITY;
                        if (c0 + 1 > rowb) Sa[nt][1] = -INFINITY;
                        if (c0 > rowb + 8)     Sa[nt][2] = -INFINITY;
                        if (c0 + 1 > rowb + 8) Sa[nt][3] = -INFINITY;
                    }
                }

                // ---- online softmax (P stays in Sa registers) ----
#pragma unroll
                for (int h = 0; h < 2; h++) {
                    float rmax = -INFINITY;
#pragma unroll
                    for (int nt = 0; nt < 8; nt++)
                        rmax = fmaxf(rmax, fmaxf(Sa[nt][2 * h], Sa[nt][2 * h + 1]));
                    rmax = fmaxf(rmax, __shfl_xor_sync(0xffffffffu, rmax, 1));
                    rmax = fmaxf(rmax, __shfl_xor_sync(0xffffffffu, rmax, 2));
                    const float mnew = fmaxf(m_i[h], rmax);
                    const float a = __expf(m_i[h] - mnew);
                    float rs = 0.f;
#pragma unroll
                    for (int nt = 0; nt < 8; nt++) {
                        const float p0 = __expf(Sa[nt][2 * h]     - mnew);
                        const float p1 = __expf(Sa[nt][2 * h + 1] - mnew);
                        Sa[nt][2 * h] = p0; Sa[nt][2 * h + 1] = p1;
                        rs += p0 + p1;
                    }
                    rs += __shfl_xor_sync(0xffffffffu, rs, 1);
                    rs += __shfl_xor_sync(0xffffffffu, rs, 2);
                    l_i[h] = l_i[h] * a + rs;
                    m_i[h] = mnew;
#pragma unroll
                    for (int nt = 0; nt < 8; nt++) {
                        Oa[nt][2 * h] *= a;
                        Oa[nt][2 * h + 1] *= a;
                    }
                }

                // ---- O += P V ----  (P A-frags packed directly from Sa)
                const uint32_t vBase = sb + (cur ? OFF_V1 : OFF_V0) * 2u
                                     + (uint32_t)(half * 64 * VSTRH) * 2u;
#pragma unroll
                for (int st = 0; st < 4; st++) {
                    uint32_t pa[4];
                    pa[0] = pack_h2(Sa[2 * st][0],     Sa[2 * st][1]);
                    pa[1] = pack_h2(Sa[2 * st][2],     Sa[2 * st][3]);
                    pa[2] = pack_h2(Sa[2 * st + 1][0], Sa[2 * st + 1][1]);
                    pa[3] = pack_h2(Sa[2 * st + 1][2], Sa[2 * st + 1][3]);
#pragma unroll
                    for (int ntp = 0; ntp < 4; ntp++) {
                        uint32_t vb[4];
                        const uint32_t addr = vBase
                            + (uint32_t)((st * 16 + vRow) * VSTRH) * 2u
                            + (uint32_t)((ntp * 16) * 2 + vChunk);
                        ldsm_x4_trans(vb, addr);
                        mma_f16(Oa[2 * ntp], pa, vb);
                        mma_f16(Oa[2 * ntp + 1], pa, vb + 2);
                    }
                }
            }
        }
    }

    // epilogue: normalize, write ctx (fp16, feeds O-GEMM) UNSCRAMBLED
    const int b_ = bgm >> 4;
    const int gb = (bgm >> 3) & 1;
    const int mp = bgm & 7;
#pragma unroll
    for (int h = 0; h < 2; h++) {
        const float inv = 1.0f / l_i[h];
        const int np = qblk * 128 + 16 * wid + g + 8 * h;
        const int flat = mp * NSEQ + np;
        const int n  = flat >> 3;
        const int mm = flat & 7;
        const int colbase = gb * 512 + mm * 64 + 2 * t;
        __half* dst = ctx + (size_t)(b_ * NSEQ + n) * EDIM;
#pragma unroll
        for (int nt = 0; nt < 8; nt++) {
            *(__half2*)(dst + colbase + nt * 8) =
                __floats2half2_rn(Oa[nt][2 * h] * inv, Oa[nt][2 * h + 1] * inv);
        }
    }
}

// ---------------------------------------------------------------------------

extern "C" void kernel_launch(void* const* d_in, const int* in_sizes, int n_in,
                              void* d_out, int out_size) {
    (void)in_sizes; (void)n_in; (void)out_size;
    const float* x  = (const float*)d_in[0];
    const float* Wq = (const float*)d_in[1];
    const float* bq = (const float*)d_in[2];
    const float* Wk = (const float*)d_in[3];
    const float* bk = (const float*)d_in[4];
    const float* Wv = (const float*)d_in[5];
    const float* bv = (const float*)d_in[6];
    const float* Wo = (const float*)d_in[7];
    const float* bo = (const float*)d_in[8];
    float* out = (float*)d_out;

    __half *pq, *pk, *pv, *pctx, *pxh, *pwh;
    cudaGetSymbolAddress((void**)&pq,   g_q);
    cudaGetSymbolAddress((void**)&pk,   g_k);
    cudaGetSymbolAddress((void**)&pv,   g_v);
    cudaGetSymbolAddress((void**)&pctx, g_ctx);
    cudaGetSymbolAddress((void**)&pxh,  g_xh);
    cudaGetSymbolAddress((void**)&pwh,  g_wh);

    cudaFuncSetAttribute(gemm_mma<true>,
                         cudaFuncAttributeMaxDynamicSharedMemorySize, GEMM_SMEM);
    cudaFuncSetAttribute(gemm_mma<false>,
                         cudaFuncAttributeMaxDynamicSharedMemorySize, GEMM_SMEM);
    cudaFuncSetAttribute(attn_mma,
                         cudaFuncAttributeMaxDynamicSharedMemorySize, ATTN_SMEM);

    // 1) convert x and all W's to fp16 scratch
    precvt<<<2048, 256>>>((const float4*)x,
                          (const float4*)Wq, (const float4*)Wk,
                          (const float4*)Wv, (const float4*)Wo,
                          (uint2*)pxh, (uint2*)pwh);

    const float scale = 0.125f;  // dh^-0.5, folded into Q (and its bias)

    // 2) QKV projections (fused z-grid), fp16 in / fp16 scrambled out
    GemmJobs qkv;
    qkv.j[0] = { pwh + 0 * (size_t)EDIM * EDIM, bq, pq, scale };
    qkv.j[1] = { pwh + 1 * (size_t)EDIM * EDIM, bk, pk, 1.0f };
    qkv.j[2] = { pwh + 2 * (size_t)EDIM * EDIM, bv, pv, 1.0f };
    gemm_mma<true><<<dim3(EDIM / BN, (NBATCH * NSEQ) / BM, 3), 256, GEMM_SMEM>>>(pxh, qkv);

    // 3) attention (fp16 operands, fp32 softmax/accum)
    attn_mma<<<dim3(NSEQ / 128, NGROUPS), 256, ATTN_SMEM>>>(pctx);

    // 4) output projection: fp16 ctx x fp16 Wo -> fp32 out
    GemmJobs oj;
    oj.j[0] = { pwh + 3 * (size_t)EDIM * EDIM, bo, out, 1.0f };
    oj.j[1] = oj.j[0];
    oj.j[2] = oj.j[0];
    gemm_mma<false><<<dim3(EDIM / BN, (NBATCH * NSEQ) / BM, 1), 256, GEMM_SMEM>>>(pctx, oj);
}

// round 17
// speedup vs baseline: 1.0484x; 1.0098x over previous
#include <cuda_runtime.h>
#include <cuda_fp16.h>
#include <math.h>
#include <stdint.h>

#define EDIM 1024
#define NSEQ 2048
#define NBATCH 2
#define DH 64
#define NGROUPS 32   /* B * N_BLOCKS * MICRO_HEADS = 2*2*8 */

// Scratch (device globals: no allocation allowed in kernel_launch)
__device__ __half g_q[NGROUPS * NSEQ * DH];
__device__ __half g_k[NGROUPS * NSEQ * DH];
__device__ __half g_v[NGROUPS * NSEQ * DH];
__device__ __half g_ctx[NBATCH * NSEQ * EDIM];
__device__ __half g_xh[NBATCH * NSEQ * EDIM];   // fp16 x
__device__ __half g_wh[4 * EDIM * EDIM];        // fp16 Wq,Wk,Wv,Wo
__device__ unsigned int g_tilectr;              // dynamic tile counter (QKV)

// ---------------------------------------------------------------------------
// helpers
// ---------------------------------------------------------------------------
__device__ __forceinline__ void mma_f16(float* c, const uint32_t* a, const uint32_t* b) {
    asm volatile(
        "mma.sync.aligned.m16n8k16.row.col.f32.f16.f16.f32 "
        "{%0,%1,%2,%3}, {%4,%5,%6,%7}, {%8,%9}, {%0,%1,%2,%3};"
        : "+f"(c[0]), "+f"(c[1]), "+f"(c[2]), "+f"(c[3])
        : "r"(a[0]), "r"(a[1]), "r"(a[2]), "r"(a[3]), "r"(b[0]), "r"(b[1]));
}

__device__ __forceinline__ void ldsm_x4(uint32_t* r, uint32_t addr) {
    asm volatile("ldmatrix.sync.aligned.m8n8.x4.shared.b16 {%0,%1,%2,%3}, [%4];"
                 : "=r"(r[0]), "=r"(r[1]), "=r"(r[2]), "=r"(r[3]) : "r"(addr));
}
__device__ __forceinline__ void ldsm_x4_trans(uint32_t* r, uint32_t addr) {
    asm volatile("ldmatrix.sync.aligned.m8n8.x4.trans.shared.b16 {%0,%1,%2,%3}, [%4];"
                 : "=r"(r[0]), "=r"(r[1]), "=r"(r[2]), "=r"(r[3]) : "r"(addr));
}

__device__ __forceinline__ uint32_t pack_h2(float lo, float hi) {
    __half2 h = __floats2half2_rn(lo, hi);
    return *(uint32_t*)&h;
}

__device__ __forceinline__ uint32_t smem_u32(const void* p) {
    uint32_t a;
    asm("{ .reg .u64 t; cvta.to.shared.u64 t, %1; cvt.u32.u64 %0, t; }" : "=r"(a) : "l"(p));
    return a;
}

__device__ __forceinline__ void cp_async16(uint32_t dst, const void* src) {
    asm volatile("cp.async.cg.shared.global [%0], [%1], 16;" :: "r"(dst), "l"(src));
}
__device__ __forceinline__ void cp_commit() {
    asm volatile("cp.async.commit_group;" ::: "memory");
}
template<int N>
__device__ __forceinline__ void cp_wait() {
    asm volatile("cp.async.wait_group %0;" :: "n"(N) : "memory");
}

// ---------------------------------------------------------------------------
// Pre-convert pass: x and all W's -> fp16 (RN). Also resets the QKV tile
// counter (precvt always precedes the QKV launch in stream order).
// ---------------------------------------------------------------------------
#define XF4 (NBATCH * NSEQ * EDIM / 4)   /* 1048576 */
#define WF4 (EDIM * EDIM / 4)            /*  262144 */
#define TOTF4 (XF4 + 4 * WF4)

__global__ __launch_bounds__(256)
void precvt(const float4* __restrict__ x,
            const float4* __restrict__ wq, const float4* __restrict__ wk,
            const float4* __restrict__ wv, const float4* __restrict__ wo,
            uint2* __restrict__ xh, uint2* __restrict__ wh)
{
    if (blockIdx.x == 0 && threadIdx.x == 0) g_tilectr = 0u;
    for (int i = blockIdx.x * blockDim.x + threadIdx.x; i < TOTF4;
         i += gridDim.x * blockDim.x) {
        const float4* src;
        uint2* dst;
        if (i < XF4) {
            src = x + i; dst = xh + i;
        } else {
            const int j = i - XF4;
            const int w = j / WF4, o = j - w * WF4;
            const float4* ws = (w == 0) ? wq : (w == 1) ? wk : (w == 2) ? wv : wo;
            src = ws + o; dst = wh + j;
        }
        float4 v = *src;
        union { __half2 h2[2]; uint2 u; } cv;
        cv.h2[0] = __floats2half2_rn(v.x, v.y);
        cv.h2[1] = __floats2half2_rn(v.z, v.w);
        *dst = cv.u;
    }
}

// ---------------------------------------------------------------------------
// fp16 HMMA GEMM tile body: occupancy-2, 3-stage cp.async pipeline, BK=64,
// ldmatrix fragment loads, mid-loop prefetch (R14-validated schedule).
// C[r][c] = alpha * (sum_k A[r][k] * W[c][k] + bias[c]),  A/W fp16, acc fp32.
// BM=128 BN=128, 256 threads, 8 warps (2m x 4n), warp 64x32.
// ---------------------------------------------------------------------------
#define BM 128
#define BN 128
#define BKH 64                          /* halfs per k-tile */
#define KSTH 72                         /* halfs row stride (=144 B) */
#define NKT (EDIM / BKH)                /* 16 */
#define NSTG 3
#define STGH ((BM + BN) * KSTH)         /* 18432 halfs = 36864 B per stage */
#define GEMM_SMEM (NSTG * STGH * 2)     /* 110592 bytes */

#define QKV_TILES 768                   /* 3 jobs x 32 by x 8 bx */
#define PERSIST_CTAS 296                /* ~2 CTAs per SM */

struct GemmJob  { const __half* W; const float* bias; void* C; float alpha; };
struct GemmJobs { GemmJob j[3]; };

template<bool SCRAMBLE>
__device__ __forceinline__ void gemm_tile(
    const __half* __restrict__ A, const GemmJob& job,
    int bx, int by, __half* shh, uint32_t sb)
{
    const __half* __restrict__ W   = job.W;
    const float* __restrict__ bias = job.bias;
    const float alpha              = job.alpha;

    const int tid  = threadIdx.x;
    const int lane = tid & 31, wid = tid >> 5;
    const int g = lane >> 2, t = lane & 3;
    const int wm = (wid >> 2) * 64;          // warp m offset: 0 / 64
    const int wn = (wid & 3) * 32;           // warp n offset: 0/32/64/96
    const int rbase = by * BM;
    const int cbase = bx * BN;

    // ldmatrix lane-address components
    const int aRow   = (lane & 15);
    const int aChunk = (lane >> 4) * 16;
    const int bRow   = (lane & 7) + (lane >> 4) * 8;
    const int bChunk = ((lane >> 3) & 1) * 16;

    auto fill = [&](int s, int kt) {
        const uint32_t stgA = sb + (uint32_t)(s * STGH) * 2u;
        const uint32_t stgB = stgA + (uint32_t)(BM * KSTH) * 2u;
#pragma unroll
        for (int j = 0; j < 4; j++) {
            const int idx = tid + j * 256;       // 0..1023
            const int r = idx >> 3, f = idx & 7;
            cp_async16(stgA + (uint32_t)(r * KSTH) * 2u + (uint32_t)f * 16u,
                       A + (size_t)(rbase + r) * EDIM + kt * BKH + f * 8);
        }
#pragma unroll
        for (int j = 0; j < 4; j++) {
            const int idx = tid + j * 256;
            const int r = idx >> 3, f = idx & 7;
            cp_async16(stgB + (uint32_t)(r * KSTH) * 2u + (uint32_t)f * 16u,
                       W + (size_t)(cbase + r) * EDIM + kt * BKH + f * 8);
        }
        cp_commit();
    };

    float accf[4][4][4];
#pragma unroll
    for (int mt = 0; mt < 4; mt++)
#pragma unroll
        for (int nt = 0; nt < 4; nt++)
#pragma unroll
            for (int q = 0; q < 4; q++) accf[mt][nt][q] = 0.f;

    fill(0, 0);
    fill(1, 1);

#pragma unroll 1
    for (int kt = 0; kt < NKT; kt++) {
        const int s = (kt % NSTG);
        if (kt == NKT - 1) cp_wait<0>();
        else               cp_wait<1>();
        __syncthreads();

        const uint32_t aBase = sb + (uint32_t)(s * STGH) * 2u;
        const uint32_t bBase = aBase + (uint32_t)(BM * KSTH) * 2u;
#pragma unroll
        for (int ks = 0; ks < 4; ks++) {         // four k16 steps cover BKH=64
            uint32_t af[4][4], bf[4][2];
#pragma unroll
            for (int mt = 0; mt < 4; mt++) {
                const uint32_t addr = aBase
                    + (uint32_t)((wm + mt * 16 + aRow) * KSTH) * 2u
                    + (uint32_t)(ks * 32 + aChunk);
                ldsm_x4(af[mt], addr);
            }
#pragma unroll
            for (int ntp = 0; ntp < 2; ntp++) {
                uint32_t r4[4];
                const uint32_t addr = bBase
                    + (uint32_t)((wn + ntp * 16 + bRow) * KSTH) * 2u
                    + (uint32_t)(ks * 32 + bChunk);
                ldsm_x4(r4, addr);
                bf[2 * ntp][0] = r4[0]; bf[2 * ntp][1] = r4[1];
                bf[2 * ntp + 1][0] = r4[2]; bf[2 * ntp + 1][1] = r4[3];
            }
#pragma unroll
            for (int mt = 0; mt < 4; mt++)
#pragma unroll
                for (int nt = 0; nt < 4; nt++)
                    mma_f16(accf[mt][nt], af[mt], bf[nt]);

            // mid-loop prefetch: after the first ks block's MMAs are issued
            if (ks == 0 && kt + 2 < NKT) fill((kt + 2) % NSTG, kt + 2);
        }
    }

    // epilogue: c0=(g,2t) c1=(g,2t+1) c2=(g+8,2t) c3=(g+8,2t+1)
#pragma unroll
    for (int nt = 0; nt < 4; nt++) {
        const int col = cbase + wn + nt * 8 + 2 * t;
        const float2 bb = *(const float2*)&bias[col];
#pragma unroll
        for (int mt = 0; mt < 4; mt++) {
#pragma unroll
            for (int h = 0; h < 2; h++) {
                const int r = rbase + wm + mt * 16 + g + h * 8;
                const float vx = alpha * (accf[mt][nt][h * 2 + 0] + bb.x);
                const float vy = alpha * (accf[mt][nt][h * 2 + 1] + bb.y);
                if (SCRAMBLE) {
                    __half* Ch = (__half*)job.C;
                    const int b_ = r >> 11;
                    const int n  = r & (NSEQ - 1);
                    const int gb = col >> 9;
                    const int mm = (col >> 6) & 7;
                    const int dd = col & 63;
                    const int flat = n * 8 + mm;
                    const int mp = flat >> 11;
                    const int np = flat & (NSEQ - 1);
                    *(__half2*)(Ch + ((size_t)((b_ * 2 + gb) * 8 + mp) * NSEQ + np) * DH + dd) =
                        __floats2half2_rn(vx, vy);
                } else {
                    float* Cf = (float*)job.C;
                    float2 v; v.x = vx; v.y = vy;
                    *(float2*)(Cf + (size_t)r * EDIM + col) = v;
                }
            }
        }
    }
}

// Persistent QKV: 296 CTAs pop tiles from the global counter. Tile decode
// puts the 3 z-jobs adjacent per (bx,by) so the shared A tile stays L2-hot.
__global__ __launch_bounds__(256, 2)
void gemm_qkv_persistent(const __half* __restrict__ A, GemmJobs jobs)
{
    extern __shared__ __half shh[];
    const uint32_t sb = smem_u32(shh);
    __shared__ unsigned int s_idx;

    for (;;) {
        if (threadIdx.x == 0) s_idx = atomicAdd(&g_tilectr, 1u);
        __syncthreads();
        const unsigned int idx = s_idx;
        if (idx >= QKV_TILES) break;

        const int z  = (int)(idx % 3u);
        const int r2 = (int)(idx / 3u);
        const int bx = r2 & 7;
        const int by = r2 >> 3;
        gemm_tile<true>(A, jobs.j[z], bx, by, shh, sb);
        __syncthreads();   // all warps done with smem before next tile's fill
    }
}

// Plain-grid GEMM (used for the O projection: 256 CTAs = 0.86 wave, fine)
template<bool SCRAMBLE>
__global__ __launch_bounds__(256, 2)
void gemm_mma(const __half* __restrict__ A, GemmJobs jobs)
{
    extern __shared__ __half shh[];
    const uint32_t sb = smem_u32(shh);
    gemm_tile<SCRAMBLE>(A, jobs.j[blockIdx.z], blockIdx.x, blockIdx.y, shh, sb);
}

// ---------------------------------------------------------------------------
// Flash attention on fp16 HMMA m16n8k16 with ldmatrix loads and
// REGISTER-DIRECT P fragments. Byte-identical to the R13/R14 kernel.
// ---------------------------------------------------------------------------
#define KSTRH 72          /* halfs row stride = 144 B */
#define VSTRH 72
#define PSTRH 72
#define OFF_K0 0
#define OFF_K1 (128 * KSTRH)                     /*  9216 halfs */
#define OFF_V0 (2 * 128 * KSTRH)                 /* 18432 */
#define OFF_V1 (OFF_V0 + 128 * VSTRH)            /* 27648 */
#define OFF_QP (OFF_V0 + 2 * 128 * VSTRH)        /* 36864 */
#define ATTN_SMEM ((OFF_QP + 128 * PSTRH) * 2)   /* 92160 bytes */

__global__ __launch_bounds__(256, 2)
void attn_mma(__half* __restrict__ ctx)
{
    extern __shared__ __half shh[];
    const uint32_t sb = smem_u32(shh);
    const int tid  = threadIdx.x;
    const int lane = tid & 31, wid = tid >> 5;
    const int g = lane >> 2, t = lane & 3;
    const int qblk = (int)gridDim.x - 1 - (int)blockIdx.x;   // long first
    const int bgm  = blockIdx.y;

    const __half* Qb = g_q + (size_t)bgm * NSEQ * DH;
    const __half* Kb = g_k + (size_t)bgm * NSEQ * DH;
    const __half* Vb = g_v + (size_t)bgm * NSEQ * DH;

    const uint32_t koff[2] = { OFF_K0 * 2u, OFF_K1 * 2u };
    const uint32_t voff[2] = { OFF_V0 * 2u, OFF_V1 * 2u };

    // ldmatrix lane-address components
    const int aRow   = (lane & 15);
    const int aChunk = (lane >> 4) * 16;
    const int bRow   = (lane & 7) + (lane >> 4) * 8;
    const int bChunk = ((lane >> 3) & 1) * 16;
    const int vRow   = (lane & 7) + ((lane >> 3) & 1) * 8;   // k within 16
    const int vChunk = (lane >> 4) * 16;                      // n halfs *2 bytes

    const int njb = qblk + 1;    // 128-row kv tiles (incl. diagonal)

    {
#pragma unroll
        for (int i = 0; i < 4; i++) {
            const int idx = tid + i * 256;           // 0..1023
            const int r = idx >> 3, f = idx & 7;
            cp_async16(sb + koff[0] + (uint32_t)(r * KSTRH) * 2u + (uint32_t)f * 16u,
                       Kb + (size_t)r * DH + f * 8);
        }
#pragma unroll
        for (int i = 0; i < 4; i++) {
            const int idx = tid + i * 256;
            const int r = idx >> 3, f = idx & 7;
            cp_async16(sb + voff[0] + (uint32_t)(r * VSTRH) * 2u + (uint32_t)f * 16u,
                       Vb + (size_t)r * DH + f * 8);
        }
        cp_commit();
    }

    // load Q tile (128 x 64 halfs) into QP staging
    {
        __half* QP = shh + OFF_QP;
#pragma unroll
        for (int i = 0; i < 4; i++) {
            const int idx = tid + i * 256;           // 0..1023
            const int r = idx >> 3, f = idx & 7;
            *(float4*)&QP[r * PSTRH + f * 8] =
                *(const float4*)(Qb + (size_t)(qblk * 128 + r) * DH + f * 8);
        }
    }
    __syncthreads();

    // Q A-fragments via ldmatrix: 4 k16-steps x 4 regs
    uint32_t qf[4][4];
    {
        const uint32_t qBase = sb + OFF_QP * 2u;
#pragma unroll
        for (int st = 0; st < 4; st++) {
            const uint32_t addr = qBase
                + (uint32_t)((16 * wid + aRow) * PSTRH) * 2u
                + (uint32_t)(st * 32 + aChunk);
            ldsm_x4(qf[st], addr);
        }
    }

    float m_i[2] = { -INFINITY, -INFINITY };
    float l_i[2] = { 0.f, 0.f };
    float Oa[8][4];
#pragma unroll
    for (int nt = 0; nt < 8; nt++)
#pragma unroll
        for (int q = 0; q < 4; q++) Oa[nt][q] = 0.f;

#pragma unroll 1
    for (int jt = 0; jt < njb; jt++) {
        const int cur = jt & 1;
        cp_wait<0>();
        __syncthreads();

        if (jt + 1 < njb) {
            const int nxt = (jt + 1) & 1;
            const __half* Ksrc = Kb + (size_t)(jt + 1) * 128 * DH;
            const __half* Vsrc = Vb + (size_t)(jt + 1) * 128 * DH;
#pragma unroll
            for (int i = 0; i < 4; i++) {
                const int idx = tid + i * 256;
                const int r = idx >> 3, f = idx & 7;
                cp_async16(sb + koff[nxt] + (uint32_t)(r * KSTRH) * 2u + (uint32_t)f * 16u,
                           Ksrc + (size_t)r * DH + f * 8);
            }
#pragma unroll
            for (int i = 0; i < 4; i++) {
                const int idx = tid + i * 256;
                const int r = idx >> 3, f = idx & 7;
                cp_async16(sb + voff[nxt] + (uint32_t)(r * VSTRH) * 2u + (uint32_t)f * 16u,
                           Vsrc + (size_t)r * DH + f * 8);
            }
            cp_commit();
        }

#pragma unroll 1
        for (int half = 0; half < 2; half++) {
            const int jb = 2 * jt + half;            // 64-col tile index
            const bool active = !(jb == 2 * qblk + 1 && wid < 4);
            if (active) {
                // ---- S = Q K^T ----
                float Sa[8][4];
#pragma unroll
                for (int nt = 0; nt < 8; nt++)
#pragma unroll
                    for (int q = 0; q < 4; q++) Sa[nt][q] = 0.f;

                const uint32_t kBase = sb + (cur ? OFF_K1 : OFF_K0) * 2u
                                     + (uint32_t)(half * 64 * KSTRH) * 2u;
#pragma unroll
                for (int st = 0; st < 4; st++) {
#pragma unroll
                    for (int ntp = 0; ntp < 4; ntp++) {
                        uint32_t r4[4];
                        const uint32_t addr = kBase
                            + (uint32_t)((ntp * 16 + bRow) * KSTRH) * 2u
                            + (uint32_t)(st * 32 + bChunk);
                        ldsm_x4(r4, addr);
                        mma_f16(Sa[2 * ntp], qf[st], r4);
                        mma_f16(Sa[2 * ntp + 1], qf[st], r4 + 2);
                    }
                }

                // ---- causal mask ----
                if (jb >= 2 * qblk) {
                    const int colb = jb * 64 + 2 * t;
                    const int rowb = qblk * 128 + 16 * wid + g;
#pragma unroll
                    for (int nt = 0; nt < 8; nt++) {
                        const int c0 = colb + nt * 8;
                        if (c0 > rowb)     Sa[nt][0] = -INFINITY;
                        if (c0 + 1 > rowb) Sa[nt][1] = -INFINITY;
                        if (c0 > rowb + 8)     Sa[nt][2] = -INFINITY;
                        if (c0 + 1 > rowb + 8) Sa[nt][3] = -INFINITY;
                    }
                }

                // ---- online softmax (P stays in Sa registers) ----
#pragma unroll
                for (int h = 0; h < 2; h++) {
                    float rmax = -INFINITY;
#pragma unroll
                    for (int nt = 0; nt < 8; nt++)
                        rmax = fmaxf(rmax, fmaxf(Sa[nt][2 * h], Sa[nt][2 * h + 1]));
                    rmax = fmaxf(rmax, __shfl_xor_sync(0xffffffffu, rmax, 1));
                    rmax = fmaxf(rmax, __shfl_xor_sync(0xffffffffu, rmax, 2));
                    const float mnew = fmaxf(m_i[h], rmax);
                    const float a = __expf(m_i[h] - mnew);
                    float rs = 0.f;
#pragma unroll
                    for (int nt = 0; nt < 8; nt++) {
                        const float p0 = __expf(Sa[nt][2 * h]     - mnew);
                        const float p1 = __expf(Sa[nt][2 * h + 1] - mnew);
                        Sa[nt][2 * h] = p0; Sa[nt][2 * h + 1] = p1;
                        rs += p0 + p1;
                    }
                    rs += __shfl_xor_sync(0xffffffffu, rs, 1);
                    rs += __shfl_xor_sync(0xffffffffu, rs, 2);
                    l_i[h] = l_i[h] * a + rs;
                    m_i[h] = mnew;
#pragma unroll
                    for (int nt = 0; nt < 8; nt++) {
                        Oa[nt][2 * h] *= a;
                        Oa[nt][2 * h + 1] *= a;
                    }
                }

                // ---- O += P V ----  (P A-frags packed directly from Sa)
                const uint32_t vBase = sb + (cur ? OFF_V1 : OFF_V0) * 2u
                                     + (uint32_t)(half * 64 * VSTRH) * 2u;
#pragma unroll
                for (int st = 0; st < 4; st++) {
                    uint32_t pa[4];
                    pa[0] = pack_h2(Sa[2 * st][0],     Sa[2 * st][1]);
                    pa[1] = pack_h2(Sa[2 * st][2],     Sa[2 * st][3]);
                    pa[2] = pack_h2(Sa[2 * st + 1][0], Sa[2 * st + 1][1]);
                    pa[3] = pack_h2(Sa[2 * st + 1][2], Sa[2 * st + 1][3]);
#pragma unroll
                    for (int ntp = 0; ntp < 4; ntp++) {
                        uint32_t vb[4];
                        const uint32_t addr = vBase
                            + (uint32_t)((st * 16 + vRow) * VSTRH) * 2u
                            + (uint32_t)((ntp * 16) * 2 + vChunk);
                        ldsm_x4_trans(vb, addr);
                        mma_f16(Oa[2 * ntp], pa, vb);
                        mma_f16(Oa[2 * ntp + 1], pa, vb + 2);
                    }
                }
            }
        }
    }

    // epilogue: normalize, write ctx (fp16, feeds O-GEMM) UNSCRAMBLED
    const int b_ = bgm >> 4;
    const int gb = (bgm >> 3) & 1;
    const int mp = bgm & 7;
#pragma unroll
    for (int h = 0; h < 2; h++) {
        const float inv = 1.0f / l_i[h];
        const int np = qblk * 128 + 16 * wid + g + 8 * h;
        const int flat = mp * NSEQ + np;
        const int n  = flat >> 3;
        const int mm = flat & 7;
        const int colbase = gb * 512 + mm * 64 + 2 * t;
        __half* dst = ctx + (size_t)(b_ * NSEQ + n) * EDIM;
#pragma unroll
        for (int nt = 0; nt < 8; nt++) {
            *(__half2*)(dst + colbase + nt * 8) =
                __floats2half2_rn(Oa[nt][2 * h] * inv, Oa[nt][2 * h + 1] * inv);
        }
    }
}

// ---------------------------------------------------------------------------

extern "C" void kernel_launch(void* const* d_in, const int* in_sizes, int n_in,
                              void* d_out, int out_size) {
    (void)in_sizes; (void)n_in; (void)out_size;
    const float* x  = (const float*)d_in[0];
    const float* Wq = (const float*)d_in[1];
    const float* bq = (const float*)d_in[2];
    const float* Wk = (const float*)d_in[3];
    const float* bk = (const float*)d_in[4];
    const float* Wv = (const float*)d_in[5];
    const float* bv = (const float*)d_in[6];
    const float* Wo = (const float*)d_in[7];
    const float* bo = (const float*)d_in[8];
    float* out = (float*)d_out;

    __half *pq, *pk, *pv, *pctx, *pxh, *pwh;
    cudaGetSymbolAddress((void**)&pq,   g_q);
    cudaGetSymbolAddress((void**)&pk,   g_k);
    cudaGetSymbolAddress((void**)&pv,   g_v);
    cudaGetSymbolAddress((void**)&pctx, g_ctx);
    cudaGetSymbolAddress((void**)&pxh,  g_xh);
    cudaGetSymbolAddress((void**)&pwh,  g_wh);

    cudaFuncSetAttribute(gemm_qkv_persistent,
                         cudaFuncAttributeMaxDynamicSharedMemorySize, GEMM_SMEM);
    cudaFuncSetAttribute(gemm_mma<false>,
                         cudaFuncAttributeMaxDynamicSharedMemorySize, GEMM_SMEM);
    cudaFuncSetAttribute(attn_mma,
                         cudaFuncAttributeMaxDynamicSharedMemorySize, ATTN_SMEM);

    // 1) convert x and all W's to fp16 scratch (+ reset QKV tile counter)
    precvt<<<2048, 256>>>((const float4*)x,
                          (const float4*)Wq, (const float4*)Wk,
                          (const float4*)Wv, (const float4*)Wo,
                          (uint2*)pxh, (uint2*)pwh);

    const float scale = 0.125f;  // dh^-0.5, folded into Q (and its bias)

    // 2) QKV projections: persistent CTAs + dynamic tile counter
    GemmJobs qkv;
    qkv.j[0] = { pwh + 0 * (size_t)EDIM * EDIM, bq, pq, scale };
    qkv.j[1] = { pwh + 1 * (size_t)EDIM * EDIM, bk, pk, 1.0f };
    qkv.j[2] = { pwh + 2 * (size_t)EDIM * EDIM, bv, pv, 1.0f };
    gemm_qkv_persistent<<<PERSIST_CTAS, 256, GEMM_SMEM>>>(pxh, qkv);

    // 3) attention (fp16 operands, fp32 softmax/accum)
    attn_mma<<<dim3(NSEQ / 128, NGROUPS), 256, ATTN_SMEM>>>(pctx);

    // 4) output projection: fp16 ctx x fp16 Wo -> fp32 out
    GemmJobs oj;
    oj.j[0] = { pwh + 3 * (size_t)EDIM * EDIM, bo, out, 1.0f };
    oj.j[1] = oj.j[0];
    oj.j[2] = oj.j[0];
    gemm_mma<false><<<dim3(EDIM / BN, (NBATCH * NSEQ) / BM, 1), 256, GEMM_SMEM>>>(pctx, oj);
}